// round 3
// baseline (speedup 1.0000x reference)
#include <cuda_runtime.h>
#include <cuda_bf16.h>
#include <math.h>
#include <stdint.h>

// Problem constants (fixed by setup_inputs)
#define T_SEQ 2048
#define EMB   2048
#define NH    32
#define NKV   8
#define HD    64
#define NBLK  32
#define WIN   256

// Scratch in device globals (no allocation allowed)
__device__ float g_q[T_SEQ * NH * HD];     // [t][h][d]
__device__ float g_k[T_SEQ * NKV * HD];    // [t][kv][d]
__device__ float g_v[T_SEQ * NKV * HD];
__device__ float g_o[T_SEQ * NH * HD];
__device__ int   g_allow[NBLK * NBLK];

// ---------------------------------------------------------------------------
// Decode rw_allow_blocks robustly (bool/int8 vs int32 vs float32).
// ---------------------------------------------------------------------------
__global__ void decode_mask_kernel(const void* p) {
    __shared__ int cnt0, cnt123;
    int tid = threadIdx.x;
    if (tid == 0) { cnt0 = 0; cnt123 = 0; }
    __syncthreads();
    const unsigned char* b = (const unsigned char*)p;
    int l0 = 0, l123 = 0;
    for (int i = tid; i < 1024; i += 256) {
        if (b[i]) { if ((i & 3) == 0) l0++; else l123++; }
    }
    atomicAdd(&cnt0, l0);
    atomicAdd(&cnt123, l123);
    __syncthreads();
    if (cnt123 == 0) {
        const int* a = (const int*)p;
        for (int i = tid; i < 1024; i += 256) g_allow[i] = (a[i] != 0);
    } else if (cnt0 == 0) {
        const float* a = (const float*)p;
        for (int i = tid; i < 1024; i += 256) g_allow[i] = (a[i] != 0.0f);
    } else {
        for (int i = tid; i < 1024; i += 256) g_allow[i] = (b[i] != 0);
    }
}

// ---------------------------------------------------------------------------
// Tensor-core GEMM core: C[M,N] = A[M,K] * B[N,K]^T, fp32 in/out.
// bf16 3-term split done at fragment-load time (registers).
// Block tile 128x128, BK=16, cp.async double-buffered raw-fp32 smem.
// 8 warps, warp tile 64x32 (m16n8k16 atoms).
// ---------------------------------------------------------------------------
#define MMA_BF16(d, a0, a1, a2, a3, b0, b1)                                   \
    asm volatile(                                                             \
        "mma.sync.aligned.m16n8k16.row.col.f32.bf16.bf16.f32 "                \
        "{%0,%1,%2,%3}, {%4,%5,%6,%7}, {%8,%9}, {%0,%1,%2,%3};"               \
        : "+f"(d[0]), "+f"(d[1]), "+f"(d[2]), "+f"(d[3])                      \
        : "r"(a0), "r"(a1), "r"(a2), "r"(a3), "r"(b0), "r"(b1))

__device__ __forceinline__ void cp16(uint32_t saddr, const float* g) {
    asm volatile("cp.async.cg.shared.global [%0], [%1], 16;" :: "r"(saddr), "l"(g));
}
__device__ __forceinline__ void cp_commit() {
    asm volatile("cp.async.commit_group;" ::: "memory");
}

// fp32x2 -> bf16x2 hi + bf16x2 lo (3-term split inputs)
__device__ __forceinline__ void cvt2(float2 f, uint32_t& hi, uint32_t& lo) {
    __nv_bfloat162 h = __floats2bfloat162_rn(f.x, f.y);
    hi = *reinterpret_cast<uint32_t*>(&h);
    __nv_bfloat162 l = __floats2bfloat162_rn(f.x - __bfloat162float(h.x),
                                             f.y - __bfloat162float(h.y));
    lo = *reinterpret_cast<uint32_t*>(&l);
}

#define BK    16
#define SPAD  20   // floats per smem row (16 data + 4 pad; 80B keeps 16B align)

__device__ __forceinline__ void gemm_core(
    const float* __restrict__ A, const float* __restrict__ B,
    float* __restrict__ C, int K, int ldc, int m0, int n0)
{
    __shared__ float sA[2][128][SPAD];
    __shared__ float sB[2][128][SPAD];

    int tid  = threadIdx.x;
    int warp = tid >> 5;
    int lane = tid & 31;
    int wm = warp & 1;           // 2 m-slots of 64
    int wn = warp >> 1;          // 4 n-slots of 32
    int qr = lane >> 2;          // 0..7
    int qc = (lane & 3) * 2;     // 0,2,4,6

    float acc[4][4][4];
#pragma unroll
    for (int i = 0; i < 4; i++)
#pragma unroll
        for (int j = 0; j < 4; j++)
#pragma unroll
            for (int e = 0; e < 4; e++) acc[i][j][e] = 0.0f;

    // copy mapping: each thread moves 2 float4 per tile
    int crow = tid >> 1;                 // 0..127
    int ccol = (tid & 1) * 8;            // 0 or 8
    const float* aSrc = A + (size_t)(m0 + crow) * K + ccol;
    const float* bSrc = B + (size_t)(n0 + crow) * K + ccol;
    uint32_t sa0 = (uint32_t)__cvta_generic_to_shared(&sA[0][crow][ccol]);
    uint32_t sb0 = (uint32_t)__cvta_generic_to_shared(&sB[0][crow][ccol]);
    const uint32_t stgOff = 128 * SPAD * 4;   // bytes between stages

    const int NITER = K / BK;

    // prologue: stage 0
    cp16(sa0,      aSrc);     cp16(sa0 + 16, aSrc + 4);
    cp16(sb0,      bSrc);     cp16(sb0 + 16, bSrc + 4);
    cp_commit();

    for (int it = 0; it < NITER; it++) {
        if (it + 1 < NITER) {
            int k0 = (it + 1) * BK;
            uint32_t st = ((it + 1) & 1) * stgOff;
            cp16(sa0 + st,      aSrc + k0);  cp16(sa0 + st + 16, aSrc + k0 + 4);
            cp16(sb0 + st,      bSrc + k0);  cp16(sb0 + st + 16, bSrc + k0 + 4);
            cp_commit();
            asm volatile("cp.async.wait_group 1;" ::: "memory");
        } else {
            asm volatile("cp.async.wait_group 0;" ::: "memory");
        }
        __syncthreads();

        int st = it & 1;
        // A fragments (hi & lo) for this K16 step
        uint32_t ah[4][4], al[4][4];
#pragma unroll
        for (int mi = 0; mi < 4; mi++) {
            int r = wm * 64 + mi * 16 + qr;
            cvt2(*(const float2*)&sA[st][r][qc],         ah[mi][0], al[mi][0]);
            cvt2(*(const float2*)&sA[st][r + 8][qc],     ah[mi][1], al[mi][1]);
            cvt2(*(const float2*)&sA[st][r][qc + 8],     ah[mi][2], al[mi][2]);
            cvt2(*(const float2*)&sA[st][r + 8][qc + 8], ah[mi][3], al[mi][3]);
        }
#pragma unroll
        for (int ni = 0; ni < 4; ni++) {
            int n = wn * 32 + ni * 8 + qr;
            uint32_t bh0, bl0, bh1, bl1;
            cvt2(*(const float2*)&sB[st][n][qc],     bh0, bl0);
            cvt2(*(const float2*)&sB[st][n][qc + 8], bh1, bl1);
#pragma unroll
            for (int mi = 0; mi < 4; mi++) {
                MMA_BF16(acc[mi][ni], ah[mi][0], ah[mi][1], ah[mi][2], ah[mi][3], bh0, bh1);
                MMA_BF16(acc[mi][ni], ah[mi][0], ah[mi][1], ah[mi][2], ah[mi][3], bl0, bl1);
                MMA_BF16(acc[mi][ni], al[mi][0], al[mi][1], al[mi][2], al[mi][3], bh0, bh1);
            }
        }
        __syncthreads();
    }

    // epilogue
#pragma unroll
    for (int mi = 0; mi < 4; mi++) {
#pragma unroll
        for (int ni = 0; ni < 4; ni++) {
            int r = m0 + wm * 64 + mi * 16 + qr;
            int cidx = n0 + wn * 32 + ni * 8 + qc;
            *(float2*)&C[(size_t)r * ldc + cidx] =
                make_float2(acc[mi][ni][0], acc[mi][ni][1]);
            *(float2*)&C[(size_t)(r + 8) * ldc + cidx] =
                make_float2(acc[mi][ni][2], acc[mi][ni][3]);
        }
    }
}

// Fused Q/K/V projection: grid (24, 16). bx 0..15 -> Q, 16..19 -> K, 20..23 -> V
__global__ __launch_bounds__(256)
void qkv_gemm(const float* __restrict__ hs,
              const float* __restrict__ Wq,
              const float* __restrict__ Wk,
              const float* __restrict__ Wv) {
    int bx = blockIdx.x;
    int m0 = blockIdx.y * 128;
    const float* B;
    float* C;
    int ldc, n0;
    if (bx < 16)      { B = Wq; C = g_q; ldc = NH * HD;  n0 = bx * 128; }
    else if (bx < 20) { B = Wk; C = g_k; ldc = NKV * HD; n0 = (bx - 16) * 128; }
    else              { B = Wv; C = g_v; ldc = NKV * HD; n0 = (bx - 20) * 128; }
    gemm_core(hs, B, C, EMB, ldc, m0, n0);
}

// Output projection: grid (16, 16)
__global__ __launch_bounds__(256)
void out_gemm(const float* __restrict__ Wo, float* __restrict__ out) {
    gemm_core(g_o, Wo, out, NH * HD * 32 / 32 == 0 ? EMB : EMB, EMB,
              blockIdx.y * 128, blockIdx.x * 128);
}

// ---------------------------------------------------------------------------
// RoPE applied in-place to q and k.
// ---------------------------------------------------------------------------
__global__ void rope_kernel(const float* __restrict__ cosb, const float* __restrict__ sinb) {
    int idx = blockIdx.x * blockDim.x + threadIdx.x;
    const int total = T_SEQ * (NH + NKV) * 32;
    if (idx >= total) return;
    int d = idx & 31;
    int rest = idx >> 5;
    int head = rest % (NH + NKV);
    int t = rest / (NH + NKV);
    float c0 = cosb[t * HD + d];
    float s0 = sinb[t * HD + d];
    float c1 = cosb[t * HD + d + 32];
    float s1 = sinb[t * HD + d + 32];
    float* base = (head < NH) ? (g_q + ((size_t)t * NH + head) * HD)
                              : (g_k + ((size_t)t * NKV + (head - NH)) * HD);
    float x0 = base[d];
    float x1 = base[d + 32];
    base[d]      = x0 * c0 - x1 * s0;
    base[d + 32] = x1 * c1 + x0 * s1;
}

// ---------------------------------------------------------------------------
// Flash-style masked attention (unchanged).
// ---------------------------------------------------------------------------
__global__ void attn_kernel() {
    int h  = blockIdx.x;
    int qb = blockIdx.y;
    int r  = threadIdx.x;
    int kv = h >> 2;
    int qi = qb * 64 + r;

    __shared__ float Kt[64][64];
    __shared__ float Vt[64][64];
    __shared__ float S[64][64];

    float qreg[64];
    const float* qrow = g_q + ((size_t)qi * NH + h) * HD;
#pragma unroll
    for (int d = 0; d < 64; d++) qreg[d] = qrow[d] * 0.125f;

    float m = -1e30f, l = 0.0f;
    float acc[64];
#pragma unroll
    for (int d = 0; d < 64; d++) acc[d] = 0.0f;

    for (int kb = 0; kb < NBLK; kb++) {
        int ba = g_allow[qb * NBLK + kb];
        bool win_possible = (kb < 4) || (kb <= qb && kb + 4 >= qb);
        if (!ba && !win_possible) continue;

        __syncthreads();
        for (int idx = r; idx < 64 * 64; idx += 64) {
            int j = idx >> 6, d = idx & 63;
            size_t goff = ((size_t)(kb * 64 + j) * NKV + kv) * HD + d;
            Kt[j][d] = g_k[goff];
            Vt[j][d] = g_v[goff];
        }
        __syncthreads();

        float mb = -1e30f;
        for (int j = 0; j < 64; j++) {
            int kj = kb * 64 + j;
            bool ok = ba || (kj < WIN) || (kj <= qi && kj + (WIN - 1) >= qi);
            float s = -1e30f;
            if (ok) {
                s = 0.0f;
#pragma unroll
                for (int d = 0; d < 64; d++) s += qreg[d] * Kt[j][d];
            }
            S[j][r] = s;
            mb = fmaxf(mb, s);
        }
        if (mb > -5e29f) {
            float mnew = fmaxf(m, mb);
            float sc = __expf(m - mnew);
            m = mnew;
            l *= sc;
#pragma unroll
            for (int d = 0; d < 64; d++) acc[d] *= sc;
            for (int j = 0; j < 64; j++) {
                float p = __expf(S[j][r] - m);
                l += p;
#pragma unroll
                for (int d = 0; d < 64; d++) acc[d] += p * Vt[j][d];
            }
        }
    }
    float inv = 1.0f / l;
    float* orow = g_o + ((size_t)qi * NH + h) * HD;
#pragma unroll
    for (int d = 0; d < 64; d++) orow[d] = acc[d] * inv;
}

// ---------------------------------------------------------------------------
extern "C" void kernel_launch(void* const* d_in, const int* in_sizes, int n_in,
                              void* d_out, int out_size) {
    const float* hs   = (const float*)d_in[0];
    const float* cosb = (const float*)d_in[1];
    const float* sinb = (const float*)d_in[2];
    const float* Wq   = (const float*)d_in[3];
    const float* Wk   = (const float*)d_in[4];
    const float* Wv   = (const float*)d_in[5];
    const float* Wo   = (const float*)d_in[6];
    const void*  allow = d_in[7];
    float* out = (float*)d_out;

    decode_mask_kernel<<<1, 256>>>(allow);

    // Fused QKV projection (tensor cores, bf16 3-term, cp.async pipeline)
    qkv_gemm<<<dim3(24, T_SEQ / 128), 256>>>(hs, Wq, Wk, Wv);

    // RoPE
    {
        int total = T_SEQ * (NH + NKV) * 32;
        rope_kernel<<<(total + 255) / 256, 256>>>(cosb, sinb);
    }

    // Masked flash attention
    attn_kernel<<<dim3(NH, NBLK), 64>>>();

    // Output projection
    out_gemm<<<dim3(EMB / 128, T_SEQ / 128), 256>>>(Wo, out);
}